// round 9
// baseline (speedup 1.0000x reference)
#include <cuda_runtime.h>

// VolumeRenderingNeuS — bit-faithful emulation of the JAX/XLA:CPU reference.
//   cumsum = reduce_window scan rewritten by XLA ReduceWindowRewriter:
//     base_length B=16; per-tile SEQUENTIAL in-order scans (acc=0 left fold);
//     tile sums scanned recursively (zero-padded to multiples of 16;
//     n<=16 -> naive sequential); combine: out = fl(excl_tile_offset + inner).
//   elementwise: logistic = 1/(1+exp(-x)); exp/log = XLA:CPU Cephes kernels;
//   strict round-to-nearest mul/add (no FMA contraction, x86 LLVM default).
//   c_excl = fl(cumsum - logx); per-ray base gather; weights + rgb sums.

#define MAXN 8000000
#define B 16

__device__ float g_alpha[MAXN];
__device__ float g_logx[MAXN];
__device__ float g_I1[MAXN];      // level-1 inner tile scans
__device__ float g_cexcl[MAXN];
__device__ float g_small[1600000];

// ---- XLA:CPU Cephes/Eigen exp (no FMA) ----
__device__ __forceinline__ float cephes_expf(float input) {
    const float exp_hi = 88.3762626647950f;
    const float exp_lo = -88.3762626647949f;
    const float log2e  = 1.44269504088896341f;
    const float c1 = 0.693359375f;
    const float c2 = -2.12194440e-4f;

    float xc = fminf(fmaxf(input, exp_lo), exp_hi);
    float fx = floorf(__fadd_rn(__fmul_rn(xc, log2e), 0.5f));
    float x = __fsub_rn(xc, __fmul_rn(c1, fx));
    x = __fsub_rn(x, __fmul_rn(c2, fx));
    float z = __fmul_rn(x, x);

    float y = __fadd_rn(__fmul_rn(x, 1.9875691500e-4f), 1.3981999507e-3f);
    y = __fadd_rn(__fmul_rn(y, x), 8.3334519073e-3f);
    y = __fadd_rn(__fmul_rn(y, x), 4.1665795894e-2f);
    y = __fadd_rn(__fmul_rn(y, x), 1.6666665459e-1f);
    y = __fadd_rn(__fmul_rn(y, x), 5.0000001201e-1f);
    y = __fadd_rn(__fmul_rn(y, z), x);
    y = __fadd_rn(1.0f, y);

    int n = (int)fx;
    float two_n = __int_as_float((n + 0x7f) << 23);
    return __fmul_rn(y, two_n);
}

// ---- XLA:CPU Cephes/Eigen log (no FMA) ----
__device__ __forceinline__ float cephes_logf(float input) {
    const float sqrt_half = 0.707106781186547524f;
    int ix = __float_as_int(input);
    int emm0 = (int)(((unsigned)ix) >> 23) - 0x7e;
    float e = (float)emm0;
    float m = __int_as_float((ix & 0x807fffff) | 0x3f000000);

    bool mask = (m < sqrt_half);
    float tmp = mask ? m : 0.0f;
    float x = __fsub_rn(m, 1.0f);
    e = __fsub_rn(e, mask ? 1.0f : 0.0f);
    x = __fadd_rn(x, tmp);

    float z = __fmul_rn(x, x);
    float y = __fadd_rn(__fmul_rn(x, 7.0376836292e-2f), -1.1514610310e-1f);
    y = __fadd_rn(__fmul_rn(y, x), 1.1676998740e-1f);
    y = __fadd_rn(__fmul_rn(y, x), -1.2420140846e-1f);
    y = __fadd_rn(__fmul_rn(y, x), 1.4249322787e-1f);
    y = __fadd_rn(__fmul_rn(y, x), -1.6668057665e-1f);
    y = __fadd_rn(__fmul_rn(y, x), 2.0000714765e-1f);
    y = __fadd_rn(__fmul_rn(y, x), -2.4999993993e-1f);
    y = __fadd_rn(__fmul_rn(y, x), 3.3333331174e-1f);
    y = __fmul_rn(y, x);
    y = __fmul_rn(y, z);
    y = __fadd_rn(__fmul_rn(e, -2.12194440e-4f), y);
    y = __fsub_rn(y, __fmul_rn(0.5f, z));
    x = __fadd_rn(x, y);
    x = __fadd_rn(__fmul_rn(e, 0.693359375f), x);
    return x;
}

__device__ __forceinline__ float xla_sigmoid(float x) {
    return __fdiv_rn(1.0f, __fadd_rn(1.0f, cephes_expf(-x)));
}

// ---------------- elementwise: alpha + log(1 - alpha + 1e-6) ----------------
__global__ void __launch_bounds__(256)
ew_kernel(const float* __restrict__ sdf, const float* __restrict__ grad,
          const float* __restrict__ dirs, const float* __restrict__ dt,
          const float* __restrict__ ca_p, const float* __restrict__ beta_p,
          float* __restrict__ alpha_out, float* __restrict__ logx_out, int N)
{
    int i = blockIdx.x * blockDim.x + threadIdx.x;
    if (i >= N) return;
    const float ca = ca_p[0];
    const float beta = beta_p[0];
    const float omca = __fsub_rn(1.0f, ca);

    float m0 = __fmul_rn(dirs[3*i+0], grad[3*i+0]);
    float m1 = __fmul_rn(dirs[3*i+1], grad[3*i+1]);
    float m2 = __fmul_rn(dirs[3*i+2], grad[3*i+2]);
    float tc = __fadd_rn(__fadd_rn(m0, m1), m2);

    float ntc = -tc;
    float A = fmaxf(__fadd_rn(__fmul_rn(ntc, 0.5f), 0.5f), 0.0f);
    float Bv = fmaxf(ntc, 0.0f);
    float ic_pos = __fadd_rn(__fmul_rn(A, omca), __fmul_rn(Bv, ca)); // -iter_cos

    float m = __fmul_rn(ic_pos, dt[i]);
    float h = __fmul_rn(m, 0.5f);                // exact
    float s = sdf[i];
    float en = __fsub_rn(s, h);                  // sdf + iter_cos*dt*0.5
    float ep = __fadd_rn(s, h);                  // sdf - iter_cos*dt*0.5

    float pc = xla_sigmoid(__fmul_rn(ep, beta)); // beta=64 exact mul
    float nc = xla_sigmoid(__fmul_rn(en, beta));

    float num = __fadd_rn(__fsub_rn(pc, nc), 1e-6f);
    float den = __fadd_rn(pc, 1e-6f);
    float a = fminf(fmaxf(__fdiv_rn(num, den), 0.0f), 1.0f);
    float om = __fadd_rn(__fsub_rn(1.0f, a), 1e-6f);
    alpha_out[i] = a;
    logx_out[i]  = cephes_logf(om);
}

// ------- up: per-tile sequential inclusive scans + tile sums (OOB = 0) ------
__global__ void __launch_bounds__(256)
up_kernel(const float* __restrict__ src, int n,
          float* __restrict__ inner, float* __restrict__ sums, int ntiles)
{
    int t = blockIdx.x * blockDim.x + threadIdx.x;
    if (t >= ntiles) return;
    int base = t * B;
    float acc = 0.0f;
    #pragma unroll
    for (int c = 0; c < B; c++) {
        int idx = base + c;
        float v = (idx < n) ? src[idx] : 0.0f;   // zero padding (exact no-op)
        acc = __fadd_rn(acc, v);
        inner[idx] = acc;
    }
    sums[t] = acc;
}

// ------- naive: sequential inclusive scan for n <= B (single thread) -------
__global__ void naive_kernel(const float* __restrict__ src, int n,
                             float* __restrict__ dst)
{
    if (threadIdx.x != 0 || blockIdx.x != 0) return;
    float acc = 0.0f;
    for (int i = 0; i < n; i++) {
        acc = __fadd_rn(acc, src[i]);
        dst[i] = acc;
    }
}

// ------- down: result[j] = fl(excl_parent[tile] + inner[j]), in place ------
__global__ void __launch_bounds__(256)
down_kernel(const float* __restrict__ parent, float* __restrict__ inner,
            int n, int ntiles)
{
    int t = blockIdx.x * blockDim.x + threadIdx.x;
    if (t >= ntiles) return;
    if (t == 0) return;                          // tile 0: offset 0, identity
    float off = parent[t - 1];
    int base = t * B;
    #pragma unroll
    for (int c = 0; c < B; c++) {
        int j = base + c;
        if (j < n) inner[j] = __fadd_rn(off, inner[j]);
    }
}

// ------- down level 1 fused with exclusive fixup: c = fl(s - logx) ---------
__global__ void __launch_bounds__(256)
down1_kernel(const float* __restrict__ parent, const float* __restrict__ inner,
             const float* __restrict__ logx, float* __restrict__ cexcl,
             int n, int ntiles)
{
    int t = blockIdx.x * blockDim.x + threadIdx.x;
    if (t >= ntiles) return;
    int base = t * B;
    if (t == 0) {
        #pragma unroll
        for (int c = 0; c < B; c++) {
            int j = base + c;
            cexcl[j] = __fsub_rn(inner[j], logx[j]);
        }
    } else {
        float off = parent[t - 1];
        #pragma unroll
        for (int c = 0; c < B; c++) {
            int j = base + c;
            float s = __fadd_rn(off, inner[j]);
            cexcl[j] = __fsub_rn(s, logx[j]);
        }
    }
}

// ---------------- final: warp-per-ray weights + rgb segment sums ----------
__global__ void __launch_bounds__(256)
final_kernel(const float* __restrict__ alpha, const float* __restrict__ cexcl,
             const float* __restrict__ rgb, const int* __restrict__ ray_ids,
             float* __restrict__ rgb_out, float* __restrict__ w_out,
             int N, int n_rays)
{
    const int r = (blockIdx.x * (blockDim.x >> 5)) + (threadIdx.x >> 5);
    const int lane = threadIdx.x & 31;
    if (r >= n_rays) return;

    int start, end;
    {
        const int target = r + (lane & 1);
        int lo = 0, hi = N;
        while (lo < hi) {
            int mid = (lo + hi) >> 1;
            if (ray_ids[mid] < target) lo = mid + 1; else hi = mid;
        }
        start = __shfl_sync(0xffffffffu, lo, 0);
        end   = __shfl_sync(0xffffffffu, lo, 1);
    }

    const float base = (start < end) ? cexcl[start] : 0.0f;
    float ax = 0.0f, ay = 0.0f, az = 0.0f;
    for (int i = start + lane; i < end; i += 32) {
        float T = cephes_expf(__fsub_rn(cexcl[i], base));
        float w = __fmul_rn(alpha[i], T);
        w_out[i] = w;
        ax = __fadd_rn(ax, __fmul_rn(w, rgb[3*i+0]));
        ay = __fadd_rn(ay, __fmul_rn(w, rgb[3*i+1]));
        az = __fadd_rn(az, __fmul_rn(w, rgb[3*i+2]));
    }
    #pragma unroll
    for (int o = 16; o; o >>= 1) {
        ax = __fadd_rn(ax, __shfl_xor_sync(0xffffffffu, ax, o));
        ay = __fadd_rn(ay, __shfl_xor_sync(0xffffffffu, ay, o));
        az = __fadd_rn(az, __shfl_xor_sync(0xffffffffu, az, o));
    }
    if (lane == 0) {
        rgb_out[3*r+0] = ax;
        rgb_out[3*r+1] = ay;
        rgb_out[3*r+2] = az;
    }
}

extern "C" void kernel_launch(void* const* d_in, const int* in_sizes, int n_in,
                              void* d_out, int out_size)
{
    const float* sdf     = (const float*)d_in[0];
    const float* grad    = (const float*)d_in[1];
    const float* dirs    = (const float*)d_in[2];
    const float* dt      = (const float*)d_in[3];
    const float* rgb     = (const float*)d_in[4];
    const float* ca      = (const float*)d_in[5];
    const float* beta    = (const float*)d_in[6];
    const int*   ray_ids = (const int*)d_in[7];

    const int N      = in_sizes[0];
    const int n_rays = (out_size - N) / 3;     // out = [n_rays,3] rgb, then [N] weights
    float* out     = (float*)d_out;
    float* rgb_out = out;
    float* w_out   = out + 3 * n_rays;

    float *pa, *plx, *pI1, *pcx, *psm;
    cudaGetSymbolAddress((void**)&pa,  g_alpha);
    cudaGetSymbolAddress((void**)&plx, g_logx);
    cudaGetSymbolAddress((void**)&pI1, g_I1);
    cudaGetSymbolAddress((void**)&pcx, g_cexcl);
    cudaGetSymbolAddress((void**)&psm, g_small);

    // ---- level table: n[k] elements at level k, T[k] tiles of 16 ----
    int n[12], T[12];
    n[1] = N;
    int lv = 1;
    while (n[lv] > B) { T[lv] = (n[lv] + B - 1) / B; n[lv + 1] = T[lv]; lv++; }
    // lv = naive level (n[lv] <= 16)

    // ---- buffer assignment in g_small ----
    float* pI[12]; float* pA[12];
    size_t off = 0;
    pI[1] = pI1;
    pA[1] = psm + off; off += (size_t)T[1];
    for (int k = 2; k < lv; k++) {
        pI[k] = psm + off; off += (size_t)T[k] * B;
        pA[k] = psm + off; off += (size_t)T[k];
    }
    float* pR = psm + off;   // inclusive scan of the top (naive) level

    // ---- launches ----
    ew_kernel<<<(N + 255) / 256, 256>>>(sdf, grad, dirs, dt, ca, beta, pa, plx, N);

    for (int k = 1; k < lv; k++) {
        const float* src = (k == 1) ? plx : pA[k - 1];
        up_kernel<<<(T[k] + 255) / 256, 256>>>(src, n[k], pI[k], pA[k], T[k]);
    }

    naive_kernel<<<1, 32>>>(pA[lv - 1], n[lv], pR);

    for (int k = lv - 1; k >= 2; k--) {
        const float* parent = (k == lv - 1) ? pR : pI[k + 1];
        down_kernel<<<(T[k] + 255) / 256, 256>>>(parent, pI[k], n[k], T[k]);
    }

    {
        const float* parent = (lv == 2) ? pR : pI[2];
        down1_kernel<<<(T[1] + 255) / 256, 256>>>(parent, pI[1], plx, pcx, N, T[1]);
    }

    const int block = 256;
    const int wpb = block / 32;
    final_kernel<<<(n_rays + wpb - 1) / wpb, block>>>(
        pa, pcx, rgb, ray_ids, rgb_out, w_out, N, n_rays);
}

// round 10
// speedup vs baseline: 1.7367x; 1.7367x over previous
#include <cuda_runtime.h>

// VolumeRenderingNeuS — bit-faithful JAX/XLA:CPU emulation (ReduceWindowRewriter
// cumsum, B=16, Cephes exp/log, strict RN ops) — restructured for speed:
//   K1 ew_fused : elementwise alpha/logx + level-1 tile scan (smem, coalesced)
//   K2 seg      : scatter searchsorted(ray_ids) -> seg_start
//   K3+ up_smem : levels 2..K-1 tile scans (smem, coalesced)
//   K  midscan  : all levels with n<=4096 in ONE block (up+naive+down)
//   K  down_elem: apply tile offsets, element-parallel coalesced
//   K  final    : inline level-1 down + exclusive fixup + weights + rgb sums
// Arithmetic is op-for-op identical to the passing R8 kernel.

#define MAXN 8000000
#define MAXR ((1 << 18) + 2)
#define PAD(j) ((j) + ((j) >> 4))

__device__ float g_alpha[MAXN];
__device__ float g_logx[MAXN];
__device__ float g_I1[MAXN];
__device__ float g_small[1200000];
__device__ int   g_seg[MAXR];

// ---- XLA:CPU Cephes/Eigen exp (no FMA) ----
__device__ __forceinline__ float cephes_expf(float input) {
    const float exp_hi = 88.3762626647950f;
    const float exp_lo = -88.3762626647949f;
    const float log2e  = 1.44269504088896341f;
    float xc = fminf(fmaxf(input, exp_lo), exp_hi);
    float fx = floorf(__fadd_rn(__fmul_rn(xc, log2e), 0.5f));
    float x = __fsub_rn(xc, __fmul_rn(0.693359375f, fx));
    x = __fsub_rn(x, __fmul_rn(-2.12194440e-4f, fx));
    float z = __fmul_rn(x, x);
    float y = __fadd_rn(__fmul_rn(x, 1.9875691500e-4f), 1.3981999507e-3f);
    y = __fadd_rn(__fmul_rn(y, x), 8.3334519073e-3f);
    y = __fadd_rn(__fmul_rn(y, x), 4.1665795894e-2f);
    y = __fadd_rn(__fmul_rn(y, x), 1.6666665459e-1f);
    y = __fadd_rn(__fmul_rn(y, x), 5.0000001201e-1f);
    y = __fadd_rn(__fmul_rn(y, z), x);
    y = __fadd_rn(1.0f, y);
    int n = (int)fx;
    return __fmul_rn(y, __int_as_float((n + 0x7f) << 23));
}

// ---- XLA:CPU Cephes/Eigen log (no FMA) ----
__device__ __forceinline__ float cephes_logf(float input) {
    const float sqrt_half = 0.707106781186547524f;
    int ix = __float_as_int(input);
    int emm0 = (int)(((unsigned)ix) >> 23) - 0x7e;
    float e = (float)emm0;
    float m = __int_as_float((ix & 0x807fffff) | 0x3f000000);
    bool mask = (m < sqrt_half);
    float tmp = mask ? m : 0.0f;
    float x = __fsub_rn(m, 1.0f);
    e = __fsub_rn(e, mask ? 1.0f : 0.0f);
    x = __fadd_rn(x, tmp);
    float z = __fmul_rn(x, x);
    float y = __fadd_rn(__fmul_rn(x, 7.0376836292e-2f), -1.1514610310e-1f);
    y = __fadd_rn(__fmul_rn(y, x), 1.1676998740e-1f);
    y = __fadd_rn(__fmul_rn(y, x), -1.2420140846e-1f);
    y = __fadd_rn(__fmul_rn(y, x), 1.4249322787e-1f);
    y = __fadd_rn(__fmul_rn(y, x), -1.6668057665e-1f);
    y = __fadd_rn(__fmul_rn(y, x), 2.0000714765e-1f);
    y = __fadd_rn(__fmul_rn(y, x), -2.4999993993e-1f);
    y = __fadd_rn(__fmul_rn(y, x), 3.3333331174e-1f);
    y = __fmul_rn(y, x);
    y = __fmul_rn(y, z);
    y = __fadd_rn(__fmul_rn(e, -2.12194440e-4f), y);
    y = __fsub_rn(y, __fmul_rn(0.5f, z));
    x = __fadd_rn(x, y);
    x = __fadd_rn(__fmul_rn(e, 0.693359375f), x);
    return x;
}

__device__ __forceinline__ float xla_sigmoid(float x) {
    return __fdiv_rn(1.0f, __fadd_rn(1.0f, cephes_expf(-x)));
}

// ---- K1: elementwise + level-1 tile scan (4096 samples / block) ----
__global__ void __launch_bounds__(256)
ew_fused_kernel(const float* __restrict__ sdf, const float* __restrict__ grad,
                const float* __restrict__ dirs, const float* __restrict__ dt,
                const float* __restrict__ ca_p, const float* __restrict__ beta_p,
                float* __restrict__ alpha_out, float* __restrict__ logx_out,
                float* __restrict__ I1, float* __restrict__ A1,
                int N, int T1)
{
    __shared__ float sm[4352];
    const int base = blockIdx.x * 4096;
    const float ca = ca_p[0];
    const float beta = beta_p[0];
    const float omca = __fsub_rn(1.0f, ca);

    #pragma unroll 1
    for (int k = 0; k < 16; k++) {
        int j = k * 256 + threadIdx.x;
        int i = base + j;
        float lx = 0.0f;
        if (i < N) {
            float m0 = __fmul_rn(dirs[3*i+0], grad[3*i+0]);
            float m1 = __fmul_rn(dirs[3*i+1], grad[3*i+1]);
            float m2 = __fmul_rn(dirs[3*i+2], grad[3*i+2]);
            float tc = __fadd_rn(__fadd_rn(m0, m1), m2);
            float ntc = -tc;
            float A = fmaxf(__fadd_rn(__fmul_rn(ntc, 0.5f), 0.5f), 0.0f);
            float Bv = fmaxf(ntc, 0.0f);
            float ic_pos = __fadd_rn(__fmul_rn(A, omca), __fmul_rn(Bv, ca));
            float m = __fmul_rn(ic_pos, dt[i]);
            float h = __fmul_rn(m, 0.5f);
            float s = sdf[i];
            float en = __fsub_rn(s, h);
            float ep = __fadd_rn(s, h);
            float pc = xla_sigmoid(__fmul_rn(ep, beta));
            float nc = xla_sigmoid(__fmul_rn(en, beta));
            float num = __fadd_rn(__fsub_rn(pc, nc), 1e-6f);
            float den = __fadd_rn(pc, 1e-6f);
            float a = fminf(fmaxf(__fdiv_rn(num, den), 0.0f), 1.0f);
            float om = __fadd_rn(__fsub_rn(1.0f, a), 1e-6f);
            alpha_out[i] = a;
            lx = cephes_logf(om);
            logx_out[i] = lx;
        }
        sm[PAD(j)] = lx;
    }
    __syncthreads();

    {
        int tg = blockIdx.x * 256 + threadIdx.x;
        if (tg < T1) {
            float acc = 0.0f;
            int jb = threadIdx.x * 16;
            #pragma unroll
            for (int c = 0; c < 16; c++) {
                int p = PAD(jb + c);
                acc = __fadd_rn(acc, sm[p]);
                sm[p] = acc;
            }
            A1[tg] = acc;
        }
    }
    __syncthreads();

    #pragma unroll 1
    for (int k = 0; k < 16; k++) {
        int j = k * 256 + threadIdx.x;
        int i = base + j;
        if (i < N) I1[i] = sm[PAD(j)];
    }
}

// ---- K2: scatter searchsorted -> seg_start ----
__global__ void __launch_bounds__(256)
seg_kernel(const int* __restrict__ ray_ids, int N, int n_rays,
           int* __restrict__ seg)
{
    int i = blockIdx.x * blockDim.x + threadIdx.x;
    if (i >= N) return;
    int cur = ray_ids[i];
    int prev = (i == 0) ? -1 : ray_ids[i - 1];
    for (int r = prev + 1; r <= cur; r++) seg[r] = i;
    if (i == N - 1)
        for (int r = cur + 1; r <= n_rays; r++) seg[r] = N;
}

// ---- up level (n > 4096): smem-staged coalesced tile scans ----
__global__ void __launch_bounds__(256)
up_smem_kernel(const float* __restrict__ src, int n, int ntiles,
               float* __restrict__ inner, float* __restrict__ sums)
{
    __shared__ float sm[4352];
    const int base = blockIdx.x * 4096;
    #pragma unroll
    for (int k = 0; k < 16; k++) {
        int j = k * 256 + threadIdx.x;
        int g = base + j;
        sm[PAD(j)] = (g < n) ? src[g] : 0.0f;   // zero pad (added below)
    }
    __syncthreads();
    {
        int tg = blockIdx.x * 256 + threadIdx.x;
        if (tg < ntiles) {
            float acc = 0.0f;
            int jb = threadIdx.x * 16;
            #pragma unroll
            for (int c = 0; c < 16; c++) {
                int p = PAD(jb + c);
                acc = __fadd_rn(acc, sm[p]);
                sm[p] = acc;
            }
            sums[tg] = acc;
        }
    }
    __syncthreads();
    #pragma unroll
    for (int k = 0; k < 16; k++) {
        int j = k * 256 + threadIdx.x;
        int g = base + j;
        if (g < n) inner[g] = sm[PAD(j)];
    }
}

// ---- midscan: full scan of n <= 4096 in one block (all inner levels) ----
__global__ void __launch_bounds__(256)
midscan_kernel(float* __restrict__ x, int n)
{
    __shared__ float sm[4400];
    int m[8], off[8];
    int L = 0; m[0] = n; off[0] = 0;
    while (m[L] > 16) {
        m[L+1] = (m[L] + 15) / 16;
        off[L+1] = off[L] + m[L];
        L++;
    }
    for (int i = threadIdx.x; i < n; i += blockDim.x) sm[i] = x[i];
    __syncthreads();

    for (int l = 0; l < L; l++) {
        for (int t = threadIdx.x; t < m[l+1]; t += blockDim.x) {
            float acc = 0.0f;
            int b = off[l] + t * 16;
            for (int c = 0; c < 16; c++) {
                int j = t * 16 + c;
                float v = (j < m[l]) ? sm[b + c] : 0.0f;
                acc = __fadd_rn(acc, v);
                if (j < m[l]) sm[b + c] = acc;
            }
            sm[off[l+1] + t] = acc;
        }
        __syncthreads();
    }
    if (threadIdx.x == 0) {
        float acc = 0.0f;
        for (int i = 0; i < m[L]; i++) {
            acc = __fadd_rn(acc, sm[off[L] + i]);
            sm[off[L] + i] = acc;
        }
    }
    __syncthreads();
    for (int l = L - 1; l >= 0; l--) {
        for (int t = threadIdx.x; t < m[l+1]; t += blockDim.x) {
            if (t == 0) continue;
            float o = sm[off[l+1] + t - 1];
            int b = off[l] + t * 16;
            for (int c = 0; c < 16; c++) {
                int j = t * 16 + c;
                if (j < m[l]) sm[b + c] = __fadd_rn(o, sm[b + c]);
            }
        }
        __syncthreads();
    }
    for (int i = threadIdx.x; i < n; i += blockDim.x) x[i] = sm[i];
}

// ---- down level: element-parallel offset apply (in place) ----
__global__ void __launch_bounds__(256)
down_elem_kernel(const float* __restrict__ parent, float* __restrict__ inner,
                 int n)
{
    int j = blockIdx.x * blockDim.x + threadIdx.x;
    if (j >= n) return;
    int t = j >> 4;
    if (t == 0) return;
    inner[j] = __fadd_rn(parent[t - 1], inner[j]);
}

// ---- final: inline down1 + exclusive fixup + weights + rgb sums ----
__global__ void __launch_bounds__(256)
final_kernel(const float* __restrict__ alpha, const float* __restrict__ logx,
             const float* __restrict__ I1, const float* __restrict__ S2,
             const float* __restrict__ rgb, const int* __restrict__ seg,
             float* __restrict__ rgb_out, float* __restrict__ w_out,
             int N, int n_rays)
{
    const int r = (blockIdx.x * (blockDim.x >> 5)) + (threadIdx.x >> 5);
    const int lane = threadIdx.x & 31;
    if (r >= n_rays) return;

    const int start = seg[r];
    const int end   = seg[r + 1];

    float base = 0.0f;
    if (start < end) {
        int t = start >> 4;
        float s = I1[start];
        if (t) s = __fadd_rn(S2[t - 1], s);
        base = __fsub_rn(s, logx[start]);
    }

    float ax = 0.0f, ay = 0.0f, az = 0.0f;
    for (int i = start + lane; i < end; i += 32) {
        int t = i >> 4;
        float s = I1[i];
        if (t) s = __fadd_rn(S2[t - 1], s);
        float c = __fsub_rn(s, logx[i]);
        float T = cephes_expf(__fsub_rn(c, base));
        float w = __fmul_rn(alpha[i], T);
        w_out[i] = w;
        ax = __fadd_rn(ax, __fmul_rn(w, rgb[3*i+0]));
        ay = __fadd_rn(ay, __fmul_rn(w, rgb[3*i+1]));
        az = __fadd_rn(az, __fmul_rn(w, rgb[3*i+2]));
    }
    #pragma unroll
    for (int o = 16; o; o >>= 1) {
        ax = __fadd_rn(ax, __shfl_xor_sync(0xffffffffu, ax, o));
        ay = __fadd_rn(ay, __shfl_xor_sync(0xffffffffu, ay, o));
        az = __fadd_rn(az, __shfl_xor_sync(0xffffffffu, az, o));
    }
    if (lane == 0) {
        rgb_out[3*r+0] = ax;
        rgb_out[3*r+1] = ay;
        rgb_out[3*r+2] = az;
    }
}

extern "C" void kernel_launch(void* const* d_in, const int* in_sizes, int n_in,
                              void* d_out, int out_size)
{
    const float* sdf     = (const float*)d_in[0];
    const float* grad    = (const float*)d_in[1];
    const float* dirs    = (const float*)d_in[2];
    const float* dt      = (const float*)d_in[3];
    const float* rgb     = (const float*)d_in[4];
    const float* ca      = (const float*)d_in[5];
    const float* beta    = (const float*)d_in[6];
    const int*   ray_ids = (const int*)d_in[7];

    const int N      = in_sizes[0];
    const int n_rays = (out_size - N) / 3;
    float* out     = (float*)d_out;
    float* rgb_out = out;
    float* w_out   = out + 3 * n_rays;

    float *pa, *plx, *pI1, *psm;
    int *pseg;
    cudaGetSymbolAddress((void**)&pa,   g_alpha);
    cudaGetSymbolAddress((void**)&plx,  g_logx);
    cudaGetSymbolAddress((void**)&pI1,  g_I1);
    cudaGetSymbolAddress((void**)&psm,  g_small);
    cudaGetSymbolAddress((void**)&pseg, g_seg);

    // level-k input lengths: nl[2] = T1 = ceil(N/16), recurse while > 4096
    int nl[12];
    nl[2] = (N + 15) / 16;
    int K = 2;
    while (nl[K] > 4096) { nl[K+1] = (nl[K] + 15) / 16; K++; }

    // buffers in g_small: A1, then (I_k, A_k) for k = 2..K-1
    float* Abuf[12]; float* Ibuf[12];
    size_t off = 0;
    Abuf[1] = psm + off; off += (size_t)nl[2];
    for (int k = 2; k < K; k++) {
        Ibuf[k] = psm + off; off += (size_t)nl[k];
        Abuf[k] = psm + off; off += (size_t)nl[k+1];
    }

    const int T1 = nl[2];

    ew_fused_kernel<<<(N + 4095) / 4096, 256>>>(
        sdf, grad, dirs, dt, ca, beta, pa, plx, pI1, Abuf[1], N, T1);

    seg_kernel<<<(N + 255) / 256, 256>>>(ray_ids, N, n_rays, pseg);

    for (int k = 2; k < K; k++) {
        int ntiles = nl[k+1];
        up_smem_kernel<<<(ntiles + 255) / 256, 256>>>(
            Abuf[k-1], nl[k], ntiles, Ibuf[k], Abuf[k]);
    }

    midscan_kernel<<<1, 256>>>(Abuf[K-1], nl[K]);

    for (int k = K - 1; k >= 2; k--) {
        const float* parent = (k == K - 1) ? Abuf[K-1] : Ibuf[k+1];
        down_elem_kernel<<<(nl[k] + 255) / 256, 256>>>(parent, Ibuf[k], nl[k]);
    }

    const float* S2 = (K == 2) ? Abuf[1] : Ibuf[2];

    const int block = 256;
    const int wpb = block / 32;
    final_kernel<<<(n_rays + wpb - 1) / wpb, block>>>(
        pa, plx, pI1, S2, rgb, pseg, rgb_out, w_out, N, n_rays);
}